// round 4
// baseline (speedup 1.0000x reference)
#include <cuda_runtime.h>
#include <cuda_bf16.h>
#include <math.h>

// ---------------------------------------------------------------------------
// Problem constants
// ---------------------------------------------------------------------------
#define N_TOK   2048
#define D_MODEL 2048
#define KV_D    512
#define D_HEAD  128
#define N_QH    16      // storage order: head = g*4 + h  (g=group, h=kv head)
#define N_KVH   4

// Scratch (static device arrays: allowed; no cudaMalloc anywhere)
__device__ float g_Q[N_TOK * D_MODEL];     // x @ Wq   [2048, 2048]
__device__ float g_K[N_TOK * KV_D];        // x @ Wk   [2048, 512]
__device__ float g_V[N_TOK * KV_D];        // x @ Wv   [2048, 512]
__device__ float g_CTX[N_TOK * D_MODEL];   // attention output [2048, 2048]

// ---------------------------------------------------------------------------
// SGEMM: C[M,N] = A[M,K] @ B[K,N], all row-major, fp32.
// 128x128 block tile, 8x8 thread tile, BK=8, 256 threads.
// Requires M%128==0, N%128==0, K%8==0 (true for all our shapes).
// ---------------------------------------------------------------------------
__global__ __launch_bounds__(256) void sgemm_kernel(
    const float* __restrict__ A, const float* __restrict__ B,
    float* __restrict__ C, int M, int N, int K)
{
    __shared__ float As[8][128];
    __shared__ float Bs[8][128];

    const int tid = threadIdx.x;
    const int tx  = tid & 15;       // 0..15
    const int ty  = tid >> 4;       // 0..15
    const int bM  = blockIdx.y * 128;
    const int bN  = blockIdx.x * 128;

    // A tile loader: 128 rows x 8 k, 2 threads/row, float4 each
    const int aRow = tid >> 1;           // 0..127
    const int aK   = (tid & 1) * 4;      // 0 or 4
    // B tile loader: 8 rows x 128 cols, 32 threads/row, float4 each
    const int bRow = tid >> 5;           // 0..7
    const int bCol = (tid & 31) * 4;     // 0..124

    const float* Aptr = A + (size_t)(bM + aRow) * K + aK;
    const float* Bptr = B + (size_t)bRow * N + bN + bCol;

    float acc[8][8];
    #pragma unroll
    for (int i = 0; i < 8; i++)
        #pragma unroll
        for (int j = 0; j < 8; j++) acc[i][j] = 0.0f;

    for (int k0 = 0; k0 < K; k0 += 8) {
        float4 av = *(const float4*)(Aptr + k0);
        float4 bv = *(const float4*)(Bptr + (size_t)k0 * N);
        __syncthreads();   // previous iteration's reads done
        As[aK + 0][aRow] = av.x;
        As[aK + 1][aRow] = av.y;
        As[aK + 2][aRow] = av.z;
        As[aK + 3][aRow] = av.w;
        *(float4*)&Bs[bRow][bCol] = bv;
        __syncthreads();

        #pragma unroll
        for (int kk = 0; kk < 8; kk++) {
            float a[8], b[8];
            #pragma unroll
            for (int i = 0; i < 8; i++) a[i] = As[kk][ty * 8 + i];
            #pragma unroll
            for (int j = 0; j < 8; j++) b[j] = Bs[kk][tx * 8 + j];
            #pragma unroll
            for (int i = 0; i < 8; i++)
                #pragma unroll
                for (int j = 0; j < 8; j++)
                    acc[i][j] = fmaf(a[i], b[j], acc[i][j]);
        }
    }

    #pragma unroll
    for (int i = 0; i < 8; i++) {
        const int row = bM + ty * 8 + i;
        float* cp = C + (size_t)row * N + bN + tx * 8;
        float4 v0 = make_float4(acc[i][0], acc[i][1], acc[i][2], acc[i][3]);
        float4 v1 = make_float4(acc[i][4], acc[i][5], acc[i][6], acc[i][7]);
        *(float4*)(cp + 0) = v0;
        *(float4*)(cp + 4) = v1;
    }
}

// ---------------------------------------------------------------------------
// RoPE (interleaved complex rotation) applied in-place to Q and K.
// pair index within head i in [0,64);  angle = t * theta^{-i/64}
// ---------------------------------------------------------------------------
__global__ void rope_kernel(float* __restrict__ Q, float* __restrict__ Km)
{
    __shared__ float invf[64];
    const int tid = threadIdx.x;
    if (tid < 64)
        invf[tid] = (float)pow(10000.0, -(double)tid / 64.0);
    __syncthreads();

    const int idx = blockIdx.x * blockDim.x + tid;
    const int totalQ = N_TOK * (D_MODEL / 2);   // 2048 * 1024
    const int totalK = N_TOK * (KV_D / 2);      // 2048 * 256

    if (idx < totalQ) {
        const int t = idx >> 10;            // token
        const int c = idx & 1023;           // pair index in row
        const int i = c & 63;               // pair index in head
        float ang = (float)t * invf[i];
        float cs = cosf(ang), sn = sinf(ang);
        float* p = Q + (size_t)t * D_MODEL + 2 * c;
        float e = p[0], o = p[1];
        p[0] = e * cs - o * sn;
        p[1] = e * sn + o * cs;
    } else if (idx < totalQ + totalK) {
        const int j = idx - totalQ;
        const int t = j >> 8;
        const int c = j & 255;
        const int i = c & 63;
        float ang = (float)t * invf[i];
        float cs = cosf(ang), sn = sinf(ang);
        float* p = Km + (size_t)t * KV_D + 2 * c;
        float e = p[0], o = p[1];
        p[0] = e * cs - o * sn;
        p[1] = e * sn + o * cs;
    }
}

// ---------------------------------------------------------------------------
// Causal flash attention, fp32.
// grid: (N/32, 16).  blockIdx.y = storage head index qh = g*4 + h.
// 128 threads: thread = qi*4 + seg ; each thread owns a 32-dim segment of one
// query row (q in regs, acc in regs).  K/V share one 64x128 smem buffer.
// ---------------------------------------------------------------------------
__global__ __launch_bounds__(128) void attn_kernel(
    const float* __restrict__ Q, const float* __restrict__ K,
    const float* __restrict__ V, float* __restrict__ ctx)
{
    __shared__ float KVs[64][128];   // 32 KB, K then V
    __shared__ float Ssm[32][64];    // 8 KB scores / probabilities

    const int qb = blockIdx.x;
    const int qh = blockIdx.y;           // storage head = g*4 + h
    const int h  = qh & 3;               // kv head
    const int ctx_head = (qh & 3) * 4 + (qh >> 2);   // output head = h*4 + g

    const int tid = threadIdx.x;
    const int qi  = tid >> 2;            // 0..31 query row in tile
    const int seg = tid & 3;             // 0..3 dim segment
    const int qrow = qb * 32 + qi;

    // load this thread's query segment (post-RoPE)
    float qreg[32];
    {
        const float* qp = Q + (size_t)qrow * D_MODEL + qh * D_HEAD + seg * 32;
        #pragma unroll
        for (int e = 0; e < 8; e++) {
            float4 v = *(const float4*)(qp + e * 4);
            qreg[e * 4 + 0] = v.x; qreg[e * 4 + 1] = v.y;
            qreg[e * 4 + 2] = v.z; qreg[e * 4 + 3] = v.w;
        }
    }

    float acc[32];
    #pragma unroll
    for (int d = 0; d < 32; d++) acc[d] = 0.0f;
    float m_i = -INFINITY, l_i = 0.0f;
    const float scale = 0.08838834764831845f;   // 1/sqrt(128)

    const int lastkb = (qb * 32 + 31) >> 6;     // inclusive

    for (int kb = 0; kb <= lastkb; kb++) {
        // ---- load K tile [64,128] ----
        __syncthreads();
        {
            const float* kp = K + (size_t)(kb * 64) * KV_D + h * D_HEAD;
            #pragma unroll
            for (int e = 0; e < 16; e++) {
                int f  = tid + e * 128;        // float4 id 0..2047
                int r  = f >> 5;
                int c4 = (f & 31) << 2;
                *(float4*)&KVs[r][c4] = *(const float4*)(kp + (size_t)r * KV_D + c4);
            }
        }
        __syncthreads();

        // ---- scores S[qi][kj] = q . k, 4-lane partial + shuffle reduce ----
        for (int kj = 0; kj < 64; kj++) {
            float s = 0.0f;
            #pragma unroll
            for (int d = 0; d < 32; d++)
                s = fmaf(qreg[d], KVs[kj][seg * 32 + d], s);
            s += __shfl_xor_sync(0xffffffffu, s, 1);
            s += __shfl_xor_sync(0xffffffffu, s, 2);
            if ((kj & 3) == seg) {
                int kglob = kb * 64 + kj;
                Ssm[qi][kj] = (kglob <= qrow) ? s * scale : -INFINITY;
            }
        }
        __syncthreads();

        // ---- online softmax update ----
        float lmax = -INFINITY;
        #pragma unroll
        for (int e = 0; e < 16; e++)
            lmax = fmaxf(lmax, Ssm[qi][seg * 16 + e]);
        lmax = fmaxf(lmax, __shfl_xor_sync(0xffffffffu, lmax, 1));
        lmax = fmaxf(lmax, __shfl_xor_sync(0xffffffffu, lmax, 2));
        float mnew = fmaxf(m_i, lmax);          // finite after kb=0 (key 0 <= qrow)
        float corr = expf(m_i - mnew);          // first iter: exp(-inf)=0

        float psum = 0.0f;
        #pragma unroll
        for (int e = 0; e < 16; e++) {
            float p = expf(Ssm[qi][seg * 16 + e] - mnew);   // masked -> 0
            Ssm[qi][seg * 16 + e] = p;
            psum += p;
        }
        psum += __shfl_xor_sync(0xffffffffu, psum, 1);
        psum += __shfl_xor_sync(0xffffffffu, psum, 2);
        l_i = l_i * corr + psum;
        m_i = mnew;
        #pragma unroll
        for (int d = 0; d < 32; d++) acc[d] *= corr;
        __syncthreads();    // P writes visible; KVs reads done -> reuse for V

        // ---- load V tile into same buffer ----
        {
            const float* vp = V + (size_t)(kb * 64) * KV_D + h * D_HEAD;
            #pragma unroll
            for (int e = 0; e < 16; e++) {
                int f  = tid + e * 128;
                int r  = f >> 5;
                int c4 = (f & 31) << 2;
                *(float4*)&KVs[r][c4] = *(const float4*)(vp + (size_t)r * KV_D + c4);
            }
        }
        __syncthreads();

        // ---- ctx accumulate: acc += P @ V ----
        for (int kj = 0; kj < 64; kj++) {
            float p = Ssm[qi][kj];
            #pragma unroll
            for (int d = 0; d < 32; d++)
                acc[d] = fmaf(p, KVs[kj][seg * 32 + d], acc[d]);
        }
    }

    // ---- write ctx (normalized), permuted head order ----
    float inv = 1.0f / l_i;
    float* op = ctx + (size_t)qrow * D_MODEL + ctx_head * D_HEAD + seg * 32;
    #pragma unroll
    for (int e = 0; e < 8; e++) {
        float4 v = make_float4(acc[e * 4 + 0] * inv, acc[e * 4 + 1] * inv,
                               acc[e * 4 + 2] * inv, acc[e * 4 + 3] * inv);
        *(float4*)(op + e * 4) = v;
    }
}

// ---------------------------------------------------------------------------
// Launch
// ---------------------------------------------------------------------------
extern "C" void kernel_launch(void* const* d_in, const int* in_sizes, int n_in,
                              void* d_out, int out_size)
{
    const float* x  = (const float*)d_in[0];
    const float* Wq = (const float*)d_in[1];
    const float* Wk = (const float*)d_in[2];
    const float* Wv = (const float*)d_in[3];
    const float* Wo = (const float*)d_in[4];
    float* out = (float*)d_out;

    float *dQ, *dK, *dV, *dC;
    cudaGetSymbolAddress((void**)&dQ, g_Q);
    cudaGetSymbolAddress((void**)&dK, g_K);
    cudaGetSymbolAddress((void**)&dV, g_V);
    cudaGetSymbolAddress((void**)&dC, g_CTX);

    // Projections
    sgemm_kernel<<<dim3(D_MODEL / 128, N_TOK / 128), 256>>>(x, Wq, dQ, N_TOK, D_MODEL, D_MODEL);
    sgemm_kernel<<<dim3(KV_D   / 128, N_TOK / 128), 256>>>(x, Wk, dK, N_TOK, KV_D,   D_MODEL);
    sgemm_kernel<<<dim3(KV_D   / 128, N_TOK / 128), 256>>>(x, Wv, dV, N_TOK, KV_D,   D_MODEL);

    // RoPE on Q and K
    {
        int total = N_TOK * (D_MODEL / 2) + N_TOK * (KV_D / 2);
        int blocks = (total + 255) / 256;
        rope_kernel<<<blocks, 256>>>(dQ, dK);
    }

    // Causal attention
    attn_kernel<<<dim3(N_TOK / 32, N_QH), 128>>>(dQ, dK, dV, dC);

    // Output projection
    sgemm_kernel<<<dim3(D_MODEL / 128, N_TOK / 128), 256>>>(dC, Wo, out, N_TOK, D_MODEL, D_MODEL);
}

// round 7
// speedup vs baseline: 1.1911x; 1.1911x over previous
#include <cuda_runtime.h>
#include <cuda_bf16.h>
#include <math.h>

// ---------------------------------------------------------------------------
// Problem constants
// ---------------------------------------------------------------------------
#define N_TOK   2048
#define D_MODEL 2048
#define KV_D    512
#define D_HEAD  128
#define N_QH    16      // storage order: head = g*4 + h  (g=group, h=kv head)
#define N_KVH   4

// Scratch (static device arrays: allowed; no cudaMalloc anywhere)
__device__ float g_Q[N_TOK * D_MODEL];     // x @ Wq   [2048, 2048]
__device__ float g_K[N_TOK * KV_D];        // x @ Wk   [2048, 512]
__device__ float g_V[N_TOK * KV_D];        // x @ Wv   [2048, 512]
__device__ float g_CTX[N_TOK * D_MODEL];   // attention output [2048, 2048]

// ---------------------------------------------------------------------------
// TF32 helpers
// ---------------------------------------------------------------------------
__device__ __forceinline__ float f2tf(float x) {
    unsigned r;
    asm("cvt.rna.tf32.f32 %0, %1;" : "=r"(r) : "f"(x));
    return __uint_as_float(r);
}
__device__ __forceinline__ unsigned fbits(float x) { return __float_as_uint(x); }

// ---------------------------------------------------------------------------
// TF32 tensor-core GEMM: C[M,N] = A[M,K] @ B[K,N], row-major fp32 in/out.
// 128x128 block tile, BK=16 double-buffered, 256 threads (8 warps).
// Warp tile 32x64 = 2 (m16) x 8 (n8) mma.m16n8k8 tiles, fp32 accum.
// Requires M%128==0, N%128==0, K%16==0.
// ---------------------------------------------------------------------------
__global__ __launch_bounds__(256) void gemm_tf32(
    const float* __restrict__ A, const float* __restrict__ B,
    float* __restrict__ C, int M, int N, int K)
{
    __shared__ float As[2][128][20];    // [m][k], pad 20 -> conflict-free frags
    __shared__ float Bs[2][16][136];    // [k][n], pad 136 -> conflict-free frags

    const int tid  = threadIdx.x;
    const int lane = tid & 31;
    const int warp = tid >> 5;
    const int gid  = lane >> 2;        // 0..7
    const int tig  = lane & 3;         // 0..3
    const int wm   = (warp & 3) * 32;  // warp m offset in block tile
    const int wn   = (warp >> 2) * 64; // warp n offset in block tile
    const int bM   = blockIdx.y * 128;
    const int bN   = blockIdx.x * 128;

    // global->smem loader coords (2 float4 per thread per tile, each matrix)
    // A tile: 128 rows x 16 k = 512 float4 ; B tile: 16 rows x 128 n = 512 float4
    float c[2][8][4];
    #pragma unroll
    for (int mt = 0; mt < 2; mt++)
        #pragma unroll
        for (int nt = 0; nt < 8; nt++)
            #pragma unroll
            for (int e = 0; e < 4; e++) c[mt][nt][e] = 0.0f;

    const int NKB = K >> 4;

    // ---- preload k-block 0 into buffer 0 ----
    {
        #pragma unroll
        for (int j = 0; j < 2; j++) {
            int id = tid + j * 256;
            int ar = id >> 2, akc = (id & 3) * 4;
            float4 av = *(const float4*)(A + (size_t)(bM + ar) * K + akc);
            As[0][ar][akc + 0] = f2tf(av.x);
            As[0][ar][akc + 1] = f2tf(av.y);
            As[0][ar][akc + 2] = f2tf(av.z);
            As[0][ar][akc + 3] = f2tf(av.w);
            int br = id >> 5, bnc = (id & 31) * 4;
            float4 bv = *(const float4*)(B + (size_t)br * N + bN + bnc);
            Bs[0][br][bnc + 0] = f2tf(bv.x);
            Bs[0][br][bnc + 1] = f2tf(bv.y);
            Bs[0][br][bnc + 2] = f2tf(bv.z);
            Bs[0][br][bnc + 3] = f2tf(bv.w);
        }
    }
    __syncthreads();

    for (int kb = 0; kb < NKB; kb++) {
        const int cur = kb & 1;
        const bool pre = (kb + 1) < NKB;
        float4 pa[2], pb[2];
        if (pre) {
            const int k0 = (kb + 1) << 4;
            #pragma unroll
            for (int j = 0; j < 2; j++) {
                int id = tid + j * 256;
                int ar = id >> 2, akc = (id & 3) * 4;
                pa[j] = *(const float4*)(A + (size_t)(bM + ar) * K + k0 + akc);
                int br = id >> 5, bnc = (id & 31) * 4;
                pb[j] = *(const float4*)(B + (size_t)(k0 + br) * N + bN + bnc);
            }
        }

        // ---- compute on buffer cur ----
        #pragma unroll
        for (int ks = 0; ks < 2; ks++) {
            const int ko = ks * 8;
            unsigned a[2][4];
            #pragma unroll
            for (int mt = 0; mt < 2; mt++) {
                const int mr = wm + mt * 16 + gid;
                a[mt][0] = fbits(As[cur][mr    ][ko + tig    ]);
                a[mt][1] = fbits(As[cur][mr + 8][ko + tig    ]);
                a[mt][2] = fbits(As[cur][mr    ][ko + tig + 4]);
                a[mt][3] = fbits(As[cur][mr + 8][ko + tig + 4]);
            }
            unsigned b[8][2];
            #pragma unroll
            for (int nt = 0; nt < 8; nt++) {
                const int nc = wn + nt * 8 + gid;
                b[nt][0] = fbits(Bs[cur][ko + tig    ][nc]);
                b[nt][1] = fbits(Bs[cur][ko + tig + 4][nc]);
            }
            #pragma unroll
            for (int mt = 0; mt < 2; mt++)
                #pragma unroll
                for (int nt = 0; nt < 8; nt++) {
                    asm volatile(
                        "mma.sync.aligned.m16n8k8.row.col.f32.tf32.tf32.f32 "
                        "{%0,%1,%2,%3}, {%4,%5,%6,%7}, {%8,%9}, {%0,%1,%2,%3};"
                        : "+f"(c[mt][nt][0]), "+f"(c[mt][nt][1]),
                          "+f"(c[mt][nt][2]), "+f"(c[mt][nt][3])
                        : "r"(a[mt][0]), "r"(a[mt][1]), "r"(a[mt][2]), "r"(a[mt][3]),
                          "r"(b[nt][0]), "r"(b[nt][1]));
                }
        }

        // ---- store prefetched tile into the other buffer ----
        if (pre) {
            const int nxt = cur ^ 1;
            #pragma unroll
            for (int j = 0; j < 2; j++) {
                int id = tid + j * 256;
                int ar = id >> 2, akc = (id & 3) * 4;
                As[nxt][ar][akc + 0] = f2tf(pa[j].x);
                As[nxt][ar][akc + 1] = f2tf(pa[j].y);
                As[nxt][ar][akc + 2] = f2tf(pa[j].z);
                As[nxt][ar][akc + 3] = f2tf(pa[j].w);
                int br = id >> 5, bnc = (id & 31) * 4;
                Bs[nxt][br][bnc + 0] = f2tf(pb[j].x);
                Bs[nxt][br][bnc + 1] = f2tf(pb[j].y);
                Bs[nxt][br][bnc + 2] = f2tf(pb[j].z);
                Bs[nxt][br][bnc + 3] = f2tf(pb[j].w);
            }
        }
        __syncthreads();
    }

    // ---- epilogue ----
    #pragma unroll
    for (int mt = 0; mt < 2; mt++) {
        #pragma unroll
        for (int nt = 0; nt < 8; nt++) {
            const int row = bM + wm + mt * 16 + gid;
            const int col = bN + wn + nt * 8 + tig * 2;
            float* p = C + (size_t)row * N + col;
            *(float2*)p            = make_float2(c[mt][nt][0], c[mt][nt][1]);
            *(float2*)(p + 8 * N)  = make_float2(c[mt][nt][2], c[mt][nt][3]);
        }
    }
}

// ---------------------------------------------------------------------------
// RoPE (interleaved complex rotation) applied in-place to Q and K.
// ---------------------------------------------------------------------------
__global__ void rope_kernel(float* __restrict__ Q, float* __restrict__ Km)
{
    __shared__ float invf[64];
    const int tid = threadIdx.x;
    if (tid < 64)
        invf[tid] = (float)pow(10000.0, -(double)tid / 64.0);
    __syncthreads();

    const int idx = blockIdx.x * blockDim.x + tid;
    const int totalQ = N_TOK * (D_MODEL / 2);
    const int totalK = N_TOK * (KV_D / 2);

    if (idx < totalQ) {
        const int t = idx >> 10;
        const int c = idx & 1023;
        const int i = c & 63;
        float ang = (float)t * invf[i];
        float cs = cosf(ang), sn = sinf(ang);
        float* p = Q + (size_t)t * D_MODEL + 2 * c;
        float e = p[0], o = p[1];
        p[0] = e * cs - o * sn;
        p[1] = e * sn + o * cs;
    } else if (idx < totalQ + totalK) {
        const int j = idx - totalQ;
        const int t = j >> 8;
        const int c = j & 255;
        const int i = c & 63;
        float ang = (float)t * invf[i];
        float cs = cosf(ang), sn = sinf(ang);
        float* p = Km + (size_t)t * KV_D + 2 * c;
        float e = p[0], o = p[1];
        p[0] = e * cs - o * sn;
        p[1] = e * sn + o * cs;
    }
}

// ---------------------------------------------------------------------------
// Causal flash attention, fp32 (unchanged from R3 passing version).
// ---------------------------------------------------------------------------
__global__ __launch_bounds__(128) void attn_kernel(
    const float* __restrict__ Q, const float* __restrict__ K,
    const float* __restrict__ V, float* __restrict__ ctx)
{
    __shared__ float KVs[64][128];
    __shared__ float Ssm[32][64];

    const int qb = blockIdx.x;
    const int qh = blockIdx.y;
    const int h  = qh & 3;
    const int ctx_head = (qh & 3) * 4 + (qh >> 2);

    const int tid = threadIdx.x;
    const int qi  = tid >> 2;
    const int seg = tid & 3;
    const int qrow = qb * 32 + qi;

    float qreg[32];
    {
        const float* qp = Q + (size_t)qrow * D_MODEL + qh * D_HEAD + seg * 32;
        #pragma unroll
        for (int e = 0; e < 8; e++) {
            float4 v = *(const float4*)(qp + e * 4);
            qreg[e * 4 + 0] = v.x; qreg[e * 4 + 1] = v.y;
            qreg[e * 4 + 2] = v.z; qreg[e * 4 + 3] = v.w;
        }
    }

    float acc[32];
    #pragma unroll
    for (int d = 0; d < 32; d++) acc[d] = 0.0f;
    float m_i = -INFINITY, l_i = 0.0f;
    const float scale = 0.08838834764831845f;

    const int lastkb = (qb * 32 + 31) >> 6;

    for (int kb = 0; kb <= lastkb; kb++) {
        __syncthreads();
        {
            const float* kp = K + (size_t)(kb * 64) * KV_D + h * D_HEAD;
            #pragma unroll
            for (int e = 0; e < 16; e++) {
                int f  = tid + e * 128;
                int r  = f >> 5;
                int c4 = (f & 31) << 2;
                *(float4*)&KVs[r][c4] = *(const float4*)(kp + (size_t)r * KV_D + c4);
            }
        }
        __syncthreads();

        for (int kj = 0; kj < 64; kj++) {
            float s = 0.0f;
            #pragma unroll
            for (int d = 0; d < 32; d++)
                s = fmaf(qreg[d], KVs[kj][seg * 32 + d], s);
            s += __shfl_xor_sync(0xffffffffu, s, 1);
            s += __shfl_xor_sync(0xffffffffu, s, 2);
            if ((kj & 3) == seg) {
                int kglob = kb * 64 + kj;
                Ssm[qi][kj] = (kglob <= qrow) ? s * scale : -INFINITY;
            }
        }
        __syncthreads();

        float lmax = -INFINITY;
        #pragma unroll
        for (int e = 0; e < 16; e++)
            lmax = fmaxf(lmax, Ssm[qi][seg * 16 + e]);
        lmax = fmaxf(lmax, __shfl_xor_sync(0xffffffffu, lmax, 1));
        lmax = fmaxf(lmax, __shfl_xor_sync(0xffffffffu, lmax, 2));
        float mnew = fmaxf(m_i, lmax);
        float corr = expf(m_i - mnew);

        float psum = 0.0f;
        #pragma unroll
        for (int e = 0; e < 16; e++) {
            float p = expf(Ssm[qi][seg * 16 + e] - mnew);
            Ssm[qi][seg * 16 + e] = p;
            psum += p;
        }
        psum += __shfl_xor_sync(0xffffffffu, psum, 1);
        psum += __shfl_xor_sync(0xffffffffu, psum, 2);
        l_i = l_i * corr + psum;
        m_i = mnew;
        #pragma unroll
        for (int d = 0; d < 32; d++) acc[d] *= corr;
        __syncthreads();

        {
            const float* vp = V + (size_t)(kb * 64) * KV_D + h * D_HEAD;
            #pragma unroll
            for (int e = 0; e < 16; e++) {
                int f  = tid + e * 128;
                int r  = f >> 5;
                int c4 = (f & 31) << 2;
                *(float4*)&KVs[r][c4] = *(const float4*)(vp + (size_t)r * KV_D + c4);
            }
        }
        __syncthreads();

        for (int kj = 0; kj < 64; kj++) {
            float p = Ssm[qi][kj];
            #pragma unroll
            for (int d = 0; d < 32; d++)
                acc[d] = fmaf(p, KVs[kj][seg * 32 + d], acc[d]);
        }
    }

    float inv = 1.0f / l_i;
    float* op = ctx + (size_t)qrow * D_MODEL + ctx_head * D_HEAD + seg * 32;
    #pragma unroll
    for (int e = 0; e < 8; e++) {
        float4 v = make_float4(acc[e * 4 + 0] * inv, acc[e * 4 + 1] * inv,
                               acc[e * 4 + 2] * inv, acc[e * 4 + 3] * inv);
        *(float4*)(op + e * 4) = v;
    }
}

// ---------------------------------------------------------------------------
// Launch
// ---------------------------------------------------------------------------
extern "C" void kernel_launch(void* const* d_in, const int* in_sizes, int n_in,
                              void* d_out, int out_size)
{
    const float* x  = (const float*)d_in[0];
    const float* Wq = (const float*)d_in[1];
    const float* Wk = (const float*)d_in[2];
    const float* Wv = (const float*)d_in[3];
    const float* Wo = (const float*)d_in[4];
    float* out = (float*)d_out;

    float *dQ, *dK, *dV, *dC;
    cudaGetSymbolAddress((void**)&dQ, g_Q);
    cudaGetSymbolAddress((void**)&dK, g_K);
    cudaGetSymbolAddress((void**)&dV, g_V);
    cudaGetSymbolAddress((void**)&dC, g_CTX);

    // Projections (TF32 tensor cores, fp32 accumulate)
    gemm_tf32<<<dim3(D_MODEL / 128, N_TOK / 128), 256>>>(x, Wq, dQ, N_TOK, D_MODEL, D_MODEL);
    gemm_tf32<<<dim3(KV_D   / 128, N_TOK / 128), 256>>>(x, Wk, dK, N_TOK, KV_D,   D_MODEL);
    gemm_tf32<<<dim3(KV_D   / 128, N_TOK / 128), 256>>>(x, Wv, dV, N_TOK, KV_D,   D_MODEL);

    // RoPE on Q and K
    {
        int total = N_TOK * (D_MODEL / 2) + N_TOK * (KV_D / 2);
        int blocks = (total + 255) / 256;
        rope_kernel<<<blocks, 256>>>(dQ, dK);
    }

    // Causal attention (fp32)
    attn_kernel<<<dim3(N_TOK / 32, N_QH), 128>>>(dQ, dK, dV, dC);

    // Output projection
    gemm_tf32<<<dim3(D_MODEL / 128, N_TOK / 128), 256>>>(dC, Wo, out, N_TOK, D_MODEL, D_MODEL);
}